// round 6
// baseline (speedup 1.0000x reference)
#include <cuda_runtime.h>
#include <cuda_bf16.h>
#include <math.h>

#define N_NODES 32768
#define N_EDGES 262144
#define HC 512

// ---------------- scratch (device globals: allocation-free) ----------------
__device__ __align__(16) float g_h0[N_NODES * HC];   // 64 MB
__device__ __align__(16) float g_h1[N_NODES * HC];   // 64 MB
__device__ __align__(16) float g_p [N_NODES * HC];   // 64 MB
__device__ __align__(16) float g_q [N_NODES * HC];   // 64 MB
__device__ float g_ex[N_EDGES * 8];                  // 8 MB
__device__ int   g_deg[N_NODES];
__device__ int   g_rowptr[N_NODES + 1];
__device__ int   g_cursor[N_NODES];
__device__ int   g_ssrc[N_EDGES];

// ---------------- sort-by-dst: histogram / scan / scatter ------------------
__global__ void hist_kernel(const int* __restrict__ dst) {
    int e = blockIdx.x * blockDim.x + threadIdx.x;
    if (e < N_EDGES) atomicAdd(&g_deg[dst[e]], 1);
}

__global__ void scan_kernel() {
    __shared__ int sdata[1024];
    int t = threadIdx.x;
    int base = t * 32;
    int local = 0;
    #pragma unroll
    for (int i = 0; i < 32; i++) local += g_deg[base + i];
    sdata[t] = local;
    __syncthreads();
    // Hillis-Steele inclusive scan over 1024 partials
    for (int off = 1; off < 1024; off <<= 1) {
        int v = (t >= off) ? sdata[t - off] : 0;
        __syncthreads();
        sdata[t] += v;
        __syncthreads();
    }
    int run = (t == 0) ? 0 : sdata[t - 1];
    #pragma unroll
    for (int i = 0; i < 32; i++) {
        g_rowptr[base + i] = run;
        g_cursor[base + i] = run;
        run += g_deg[base + i];
    }
    if (t == 1023) g_rowptr[N_NODES] = run;
}

__global__ void scatter_kernel(const int* __restrict__ src, const int* __restrict__ dst) {
    int e = blockIdx.x * blockDim.x + threadIdx.x;
    if (e < N_EDGES) {
        int pos = atomicAdd(&g_cursor[dst[e]], 1);
        g_ssrc[pos] = src[e];
    }
}

// ---------------- fp32 GEMM: C[M,N] = A[M,K] @ B[K,N] (+ bias) -------------
#define BM 128
#define BN 128
#define BK 8
#define TM 8
#define TN 8

__global__ __launch_bounds__(256)
void gemm_bias_kernel(const float* __restrict__ A, const float* __restrict__ B,
                      const float* __restrict__ bias, float* __restrict__ C,
                      int M, int K, int N) {
    __shared__ float As[BK][BM + 4];   // +4 pad: conflict-free transposed stores
    __shared__ float Bs[BK][BN];

    int tid = threadIdx.x;
    int row0 = blockIdx.y * BM;
    int col0 = blockIdx.x * BN;

    int a_k = tid % BK;       // 0..7
    int a_r = tid / BK;       // 0..31 (stride 32, 4 iters)
    int b_n = tid % BN;       // 0..127
    int b_k = tid / BN;       // 0..1  (stride 2, 4 iters)

    int ty = tid / 16;        // 0..15 -> row tile
    int tx = tid % 16;        // 0..15 -> col tile

    float acc[TM][TN];
    #pragma unroll
    for (int i = 0; i < TM; i++)
        #pragma unroll
        for (int j = 0; j < TN; j++) acc[i][j] = 0.f;

    for (int k0 = 0; k0 < K; k0 += BK) {
        #pragma unroll
        for (int i = 0; i < 4; i++) {
            int r = a_r + i * 32;
            int k = k0 + a_k;
            As[a_k][r] = (k < K) ? A[(long)(row0 + r) * K + k] : 0.f;
        }
        #pragma unroll
        for (int i = 0; i < 4; i++) {
            int kk = b_k + i * 2;
            Bs[kk][b_n] = (k0 + kk < K) ? B[(long)(k0 + kk) * N + col0 + b_n] : 0.f;
        }
        __syncthreads();
        #pragma unroll
        for (int kk = 0; kk < BK; kk++) {
            float aF[TM], bF[TN];
            #pragma unroll
            for (int i = 0; i < TM; i++) aF[i] = As[kk][ty * TM + i];
            #pragma unroll
            for (int j = 0; j < TN; j++) bF[j] = Bs[kk][tx * TN + j];
            #pragma unroll
            for (int i = 0; i < TM; i++)
                #pragma unroll
                for (int j = 0; j < TN; j++)
                    acc[i][j] = fmaf(aF[i], bF[j], acc[i][j]);
        }
        __syncthreads();
    }

    #pragma unroll
    for (int i = 0; i < TM; i++) {
        int r = row0 + ty * TM + i;
        #pragma unroll
        for (int j = 0; j < TN; j++) {
            int c = col0 + tx * TN + j;
            float v = acc[i][j];
            if (bias) v += bias[c];
            C[(long)r * N + c] = v;
        }
    }
}

// ---------------- fused per-dst attention + aggregation ---------------------
// One warp per dst node. Row layout: 512 f32 = 128 float4; lane l handles
// float4 indices {j*32 + l : j=0..3}; head of index i4 = i4/16 = 2j + (l>>4).
__device__ __forceinline__ float lrelu(float v) { return v > 0.f ? v : 0.01f * v; }

__global__ __launch_bounds__(256)
void edge_kernel(const float4* __restrict__ p4, const float4* __restrict__ q4,
                 const float4* __restrict__ w4, const float4* __restrict__ h4,
                 float4* __restrict__ out4) {
    int warp = (blockIdx.x * blockDim.x + threadIdx.x) >> 5;
    int lane = threadIdx.x & 31;
    if (warp >= N_NODES) return;
    int d = warp;
    int start = g_rowptr[d];
    int end   = g_rowptr[d + 1];
    int half  = lane >> 4;

    float4 qv[4], wv[4];
    #pragma unroll
    for (int j = 0; j < 4; j++) {
        qv[j] = q4[d * 128 + j * 32 + lane];
        wv[j] = w4[j * 32 + lane];
    }

    // pass 1: scores -> exp -> per-head denominators (warp-local, no atomics)
    float den[4] = {0.f, 0.f, 0.f, 0.f};
    for (int pos = start; pos < end; pos++) {
        int s = g_ssrc[pos];
        #pragma unroll
        for (int j = 0; j < 4; j++) {
            float4 pv = p4[s * 128 + j * 32 + lane];
            float part = lrelu(pv.x + qv[j].x) * wv[j].x
                       + lrelu(pv.y + qv[j].y) * wv[j].y
                       + lrelu(pv.z + qv[j].z) * wv[j].z
                       + lrelu(pv.w + qv[j].w) * wv[j].w;
            #pragma unroll
            for (int off = 8; off >= 1; off >>= 1)
                part += __shfl_xor_sync(0xffffffffu, part, off);
            // all 16 lanes of this half now hold head (2j+half) score
            float ex = expf(part);
            den[j] += ex;
            if ((lane & 15) == j)
                g_ex[pos * 8 + 2 * j + half] = ex;
        }
    }
    __syncwarp();

    float rden[4];
    #pragma unroll
    for (int j = 0; j < 4; j++) rden[j] = (den[j] > 0.f) ? (1.f / den[j]) : 0.f;

    // pass 2: alpha-weighted aggregation in registers
    float4 acc[4];
    #pragma unroll
    for (int j = 0; j < 4; j++) acc[j] = make_float4(0.f, 0.f, 0.f, 0.f);

    for (int pos = start; pos < end; pos++) {
        int s = g_ssrc[pos];
        #pragma unroll
        for (int j = 0; j < 4; j++) {
            float a = g_ex[pos * 8 + 2 * j + half] * rden[j];
            float4 hv = h4[s * 128 + j * 32 + lane];
            acc[j].x = fmaf(hv.x, a, acc[j].x);
            acc[j].y = fmaf(hv.y, a, acc[j].y);
            acc[j].z = fmaf(hv.z, a, acc[j].z);
            acc[j].w = fmaf(hv.w, a, acc[j].w);
        }
    }

    #pragma unroll
    for (int j = 0; j < 4; j++)
        out4[d * 128 + j * 32 + lane] = acc[j];
}

// ---------------- host launch ----------------------------------------------
extern "C" void kernel_launch(void* const* d_in, const int* in_sizes, int n_in,
                              void* d_out, int out_size) {
    const float* x    = (const float*)d_in[0];   // [32768, 118]
    const int*   src  = (const int*)  d_in[2];   // [262144]
    const int*   dst  = (const int*)  d_in[3];   // [262144]
    const float* Wn   = (const float*)d_in[4];   // [118, 512]
    const float* bn   = (const float*)d_in[5];   // [512]
    const float* Wa   = (const float*)d_in[8];   // [1024, 512]
    const float* ba   = (const float*)d_in[9];   // [512]
    const float* attn = (const float*)d_in[10];  // [8, 64] = 512

    float *h0, *h1, *p, *q;
    int *deg;
    cudaGetSymbolAddress((void**)&h0, g_h0);
    cudaGetSymbolAddress((void**)&h1, g_h1);
    cudaGetSymbolAddress((void**)&p,  g_p);
    cudaGetSymbolAddress((void**)&q,  g_q);
    cudaGetSymbolAddress((void**)&deg, g_deg);

    // --- sort edges by dst (once; dst is layer-invariant) ---
    cudaMemsetAsync(deg, 0, N_NODES * sizeof(int));
    hist_kernel<<<(N_EDGES + 255) / 256, 256>>>(dst);
    scan_kernel<<<1, 1024>>>();
    scatter_kernel<<<(N_EDGES + 255) / 256, 256>>>(src, dst);

    // --- h0 = x @ Wn + bn ---
    dim3 gdim(HC / BN, N_NODES / BM);  // (4, 256)
    gemm_bias_kernel<<<gdim, 256>>>(x, Wn, bn, h0, N_NODES, 118, HC);

    const float* Wa_top = Wa;             // rows [0,512)   -> multiplies h[src]
    const float* Wa_bot = Wa + 512 * HC;  // rows [512,1024)-> multiplies h[dst]

    // --- layer 0: h0 -> h1 ---
    gemm_bias_kernel<<<gdim, 256>>>(h0, Wa_top, nullptr, p, N_NODES, HC, HC);
    gemm_bias_kernel<<<gdim, 256>>>(h0, Wa_bot, ba,      q, N_NODES, HC, HC);
    edge_kernel<<<N_NODES / 8, 256>>>((const float4*)p, (const float4*)q,
                                      (const float4*)attn, (const float4*)h0,
                                      (float4*)h1);

    // --- layer 1: h1 -> d_out ---
    gemm_bias_kernel<<<gdim, 256>>>(h1, Wa_top, nullptr, p, N_NODES, HC, HC);
    gemm_bias_kernel<<<gdim, 256>>>(h1, Wa_bot, ba,      q, N_NODES, HC, HC);
    edge_kernel<<<N_NODES / 8, 256>>>((const float4*)p, (const float4*)q,
                                      (const float4*)attn, (const float4*)h1,
                                      (float4*)d_out);
}

// round 10
// speedup vs baseline: 2.3633x; 2.3633x over previous
#include <cuda_runtime.h>
#include <cuda_bf16.h>
#include <math.h>
#include <stdint.h>

#define N_NODES 32768
#define N_EDGES 262144
#define HC 512

// ---------------- scratch (device globals: allocation-free) ----------------
__device__ __align__(16) float g_h0[N_NODES * HC];
__device__ __align__(16) float g_h1[N_NODES * HC];
__device__ __align__(16) float g_p [N_NODES * HC];
__device__ __align__(16) float g_q [N_NODES * HC];
__device__ __align__(16) __nv_bfloat16 g_ahi[N_NODES * HC];      // split of h
__device__ __align__(16) __nv_bfloat16 g_alo[N_NODES * HC];
__device__ __align__(16) __nv_bfloat16 g_xhi[N_NODES * 128];     // split of x (K padded 118->128)
__device__ __align__(16) __nv_bfloat16 g_xlo[N_NODES * 128];
__device__ __align__(16) __nv_bfloat16 g_wn_hi[512 * 128];       // Wn^T split, [N=512, Kpad=128]
__device__ __align__(16) __nv_bfloat16 g_wn_lo[512 * 128];
__device__ __align__(16) __nv_bfloat16 g_wt_hi[512 * 512];       // Wa_top^T split
__device__ __align__(16) __nv_bfloat16 g_wt_lo[512 * 512];
__device__ __align__(16) __nv_bfloat16 g_wb_hi[512 * 512];       // Wa_bot^T split
__device__ __align__(16) __nv_bfloat16 g_wb_lo[512 * 512];
__device__ float g_ex[N_EDGES * 8];
__device__ int   g_deg[N_NODES];
__device__ int   g_rowptr[N_NODES + 1];
__device__ int   g_cursor[N_NODES];
__device__ int   g_ssrc[N_EDGES];

// ---------------- warp-MMA helpers (baseline PTX, works on plain sm_103) ---
__device__ __forceinline__ uint32_t smem_u32(const void* p) {
    uint32_t a;
    asm("{ .reg .u64 t; cvta.to.shared.u64 t, %1; cvt.u32.u64 %0, t; }" : "=r"(a) : "l"(p));
    return a;
}
__device__ __forceinline__ void ldsm_x4(uint32_t* r, uint32_t addr) {
    asm volatile("ldmatrix.sync.aligned.m8n8.x4.shared.b16 {%0,%1,%2,%3}, [%4];"
                 : "=r"(r[0]), "=r"(r[1]), "=r"(r[2]), "=r"(r[3]) : "r"(addr));
}
__device__ __forceinline__ void mma16816(float* c, const uint32_t* a, const uint32_t* b) {
    asm volatile(
        "mma.sync.aligned.m16n8k16.row.col.f32.bf16.bf16.f32 "
        "{%0,%1,%2,%3}, {%4,%5,%6,%7}, {%8,%9}, {%0,%1,%2,%3};"
        : "+f"(c[0]), "+f"(c[1]), "+f"(c[2]), "+f"(c[3])
        : "r"(a[0]), "r"(a[1]), "r"(a[2]), "r"(a[3]), "r"(b[0]), "r"(b[1]));
}

// ---------------- sort-by-dst: histogram / scan / scatter ------------------
__global__ void hist_kernel(const int* __restrict__ dst) {
    int e = blockIdx.x * blockDim.x + threadIdx.x;
    if (e < N_EDGES) atomicAdd(&g_deg[dst[e]], 1);
}

__global__ void scan_kernel() {
    __shared__ int sdata[1024];
    int t = threadIdx.x;
    int base = t * 32;
    int local = 0;
    #pragma unroll
    for (int i = 0; i < 32; i++) local += g_deg[base + i];
    sdata[t] = local;
    __syncthreads();
    for (int off = 1; off < 1024; off <<= 1) {
        int v = (t >= off) ? sdata[t - off] : 0;
        __syncthreads();
        sdata[t] += v;
        __syncthreads();
    }
    int run = (t == 0) ? 0 : sdata[t - 1];
    #pragma unroll
    for (int i = 0; i < 32; i++) {
        g_rowptr[base + i] = run;
        g_cursor[base + i] = run;
        run += g_deg[base + i];
    }
    if (t == 1023) g_rowptr[N_NODES] = run;
}

__global__ void scatter_kernel(const int* __restrict__ src, const int* __restrict__ dst) {
    int e = blockIdx.x * blockDim.x + threadIdx.x;
    if (e < N_EDGES) {
        int pos = atomicAdd(&g_cursor[dst[e]], 1);
        g_ssrc[pos] = src[e];
    }
}

// ---------------- fp32 -> bf16 hi/lo split kernels --------------------------
__device__ __forceinline__ void split1(float f, uint16_t& h, uint16_t& l) {
    __nv_bfloat16 bh = __float2bfloat16(f);
    float r = f - __bfloat162float(bh);
    __nv_bfloat16 bl = __float2bfloat16(r);
    h = *reinterpret_cast<uint16_t*>(&bh);
    l = *reinterpret_cast<uint16_t*>(&bl);
}

__global__ __launch_bounds__(256)
void split_h_kernel(const float4* __restrict__ in, uint2* __restrict__ hi, uint2* __restrict__ lo) {
    int i = blockIdx.x * blockDim.x + threadIdx.x;     // over N*HC/4
    float4 v = in[i];
    uint16_t h0,l0,h1,l1,h2,l2,h3,l3;
    split1(v.x, h0, l0); split1(v.y, h1, l1); split1(v.z, h2, l2); split1(v.w, h3, l3);
    hi[i] = make_uint2((uint32_t)h0 | ((uint32_t)h1 << 16), (uint32_t)h2 | ((uint32_t)h3 << 16));
    lo[i] = make_uint2((uint32_t)l0 | ((uint32_t)l1 << 16), (uint32_t)l2 | ((uint32_t)l3 << 16));
}

__global__ __launch_bounds__(256)
void split_pad_x_kernel(const float* __restrict__ x) {
    int i = blockIdx.x * blockDim.x + threadIdx.x;     // over N*128
    int r = i >> 7, c = i & 127;
    float v = (c < 118) ? x[r * 118 + c] : 0.f;
    uint16_t h, l; split1(v, h, l);
    *reinterpret_cast<uint16_t*>(&g_xhi[i]) = h;
    *reinterpret_cast<uint16_t*>(&g_xlo[i]) = l;
}

__global__ __launch_bounds__(256)
void transpose_split_kernel(const float* __restrict__ W, int K, int Kpad,
                            __nv_bfloat16* __restrict__ bh, __nv_bfloat16* __restrict__ bl) {
    int i = blockIdx.x * blockDim.x + threadIdx.x;     // over 512*Kpad
    if (i >= 512 * Kpad) return;
    int n = i / Kpad, k = i % Kpad;
    float v = (k < K) ? W[k * 512 + n] : 0.f;
    uint16_t h, l; split1(v, h, l);
    *reinterpret_cast<uint16_t*>(&bh[i]) = h;
    *reinterpret_cast<uint16_t*>(&bl[i]) = l;
}

// ---------------- HMMA bf16x3 GEMM: C[M,512] = A @ B^T (+bias) -------------
// A (hi/lo): [M, ldk] bf16 row-major.  B (hi/lo): [512, ldk] bf16 row-major.
// TN layout -> both fragments load with non-transposed ldmatrix.
// C = Ahi*Bhi + Ahi*Blo + Alo*Bhi  (fp32 accum in registers).
#define ASTR 40   // padded smem row stride (elems); 80B -> conflict-free ldmatrix

__global__ __launch_bounds__(256, 2)
void gemm_mma_kernel(const __nv_bfloat16* __restrict__ Ahi, const __nv_bfloat16* __restrict__ Alo,
                     const __nv_bfloat16* __restrict__ Bhi, const __nv_bfloat16* __restrict__ Blo,
                     const float* __restrict__ bias, float* __restrict__ C, int ldk) {
    __shared__ __nv_bfloat16 sAhi[128 * ASTR];
    __shared__ __nv_bfloat16 sAlo[128 * ASTR];
    __shared__ __nv_bfloat16 sBhi[128 * ASTR];
    __shared__ __nv_bfloat16 sBlo[128 * ASTR];

    const int tid  = threadIdx.x;
    const int lane = tid & 31;
    const int wid  = tid >> 5;
    const int wr   = wid >> 1;        // warp row 0..3 (32 rows each)
    const int wc   = wid & 1;         // warp col 0..1 (64 cols each)
    const int row0 = blockIdx.y * 128;
    const int col0 = blockIdx.x * 128;

    float acc[2][8][4];
    #pragma unroll
    for (int mt = 0; mt < 2; mt++)
        #pragma unroll
        for (int nt = 0; nt < 8; nt++)
            #pragma unroll
            for (int k = 0; k < 4; k++) acc[mt][nt][k] = 0.f;

    const int r  = tid >> 2;          // 0..63
    const int c8 = (tid & 3) * 8;     // 0,8,16,24

    const int stages = ldk >> 5;
    for (int kt = 0; kt < stages; kt++) {
        const size_t kofs = (size_t)kt * 32 + c8;
        #pragma unroll
        for (int i = 0; i < 2; i++) {
            int rr = r + i * 64;
            *(float4*)&sAhi[rr * ASTR + c8] = *(const float4*)(Ahi + (size_t)(row0 + rr) * ldk + kofs);
            *(float4*)&sAlo[rr * ASTR + c8] = *(const float4*)(Alo + (size_t)(row0 + rr) * ldk + kofs);
            *(float4*)&sBhi[rr * ASTR + c8] = *(const float4*)(Bhi + (size_t)(col0 + rr) * ldk + kofs);
            *(float4*)&sBlo[rr * ASTR + c8] = *(const float4*)(Blo + (size_t)(col0 + rr) * ldk + kofs);
        }
        __syncthreads();

        #pragma unroll
        for (int kc = 0; kc < 2; kc++) {
            // A fragments: [hi/lo][mt][4]
            uint32_t af[2][2][4];
            {
                int arow = wr * 32 + (lane & 7) + ((lane >> 3) & 1) * 8;
                int akol = kc * 16 + (lane >> 4) * 8;
                #pragma unroll
                for (int mt = 0; mt < 2; mt++) {
                    int o = (arow + mt * 16) * ASTR + akol;
                    ldsm_x4(af[0][mt], smem_u32(&sAhi[o]));
                    ldsm_x4(af[1][mt], smem_u32(&sAlo[o]));
                }
            }
            int nrow = wc * 64 + (lane & 7) + (lane >> 4) * 8;
            int nkol = kc * 16 + ((lane >> 3) & 1) * 8;
            #pragma unroll
            for (int np = 0; np < 4; np++) {     // pairs of n8 tiles
                uint32_t bf[2][4];
                int o = (nrow + np * 16) * ASTR + nkol;
                ldsm_x4(bf[0], smem_u32(&sBhi[o]));
                ldsm_x4(bf[1], smem_u32(&sBlo[o]));
                #pragma unroll
                for (int mt = 0; mt < 2; mt++)
                    #pragma unroll
                    for (int s = 0; s < 2; s++) {
                        float* c = acc[mt][np * 2 + s];
                        mma16816(c, af[0][mt], bf[0] + s * 2);   // hi*hi
                        mma16816(c, af[0][mt], bf[1] + s * 2);   // hi*lo
                        mma16816(c, af[1][mt], bf[0] + s * 2);   // lo*hi
                    }
            }
        }
        __syncthreads();
    }

    // epilogue: c0,c1 at (row, col..col+1); c2,c3 at (row+8, col..col+1)
    #pragma unroll
    for (int mt = 0; mt < 2; mt++) {
        int rr = row0 + wr * 32 + mt * 16 + (lane >> 2);
        #pragma unroll
        for (int nt = 0; nt < 8; nt++) {
            int cc = col0 + wc * 64 + nt * 8 + (lane & 3) * 2;
            float b0 = bias ? bias[cc]     : 0.f;
            float b1 = bias ? bias[cc + 1] : 0.f;
            float2 v01 = make_float2(acc[mt][nt][0] + b0, acc[mt][nt][1] + b1);
            float2 v23 = make_float2(acc[mt][nt][2] + b0, acc[mt][nt][3] + b1);
            *(float2*)&C[(size_t)rr * HC + cc]       = v01;
            *(float2*)&C[(size_t)(rr + 8) * HC + cc] = v23;
        }
    }
}

// ---------------- fused per-dst attention + aggregation ---------------------
__device__ __forceinline__ float lrelu(float v) { return v > 0.f ? v : 0.01f * v; }

__global__ __launch_bounds__(256)
void edge_kernel(const float4* __restrict__ p4, const float4* __restrict__ q4,
                 const float4* __restrict__ w4, const float4* __restrict__ h4,
                 float4* __restrict__ out4) {
    int warp = (blockIdx.x * blockDim.x + threadIdx.x) >> 5;
    int lane = threadIdx.x & 31;
    if (warp >= N_NODES) return;
    int d = warp;
    int start = g_rowptr[d];
    int end   = g_rowptr[d + 1];
    int half  = lane >> 4;

    float4 qv[4], wv[4];
    #pragma unroll
    for (int j = 0; j < 4; j++) {
        qv[j] = q4[d * 128 + j * 32 + lane];
        wv[j] = w4[j * 32 + lane];
    }

    float den[4] = {0.f, 0.f, 0.f, 0.f};
    for (int pos = start; pos < end; pos++) {
        int s = g_ssrc[pos];
        #pragma unroll
        for (int j = 0; j < 4; j++) {
            float4 pv = p4[s * 128 + j * 32 + lane];
            float part = lrelu(pv.x + qv[j].x) * wv[j].x
                       + lrelu(pv.y + qv[j].y) * wv[j].y
                       + lrelu(pv.z + qv[j].z) * wv[j].z
                       + lrelu(pv.w + qv[j].w) * wv[j].w;
            #pragma unroll
            for (int off = 8; off >= 1; off >>= 1)
                part += __shfl_xor_sync(0xffffffffu, part, off);
            float ex = expf(part);
            den[j] += ex;
            if ((lane & 15) == j)
                g_ex[pos * 8 + 2 * j + half] = ex;
        }
    }
    __syncwarp();

    float rden[4];
    #pragma unroll
    for (int j = 0; j < 4; j++) rden[j] = (den[j] > 0.f) ? (1.f / den[j]) : 0.f;

    float4 acc[4];
    #pragma unroll
    for (int j = 0; j < 4; j++) acc[j] = make_float4(0.f, 0.f, 0.f, 0.f);

    for (int pos = start; pos < end; pos++) {
        int s = g_ssrc[pos];
        #pragma unroll
        for (int j = 0; j < 4; j++) {
            float a = g_ex[pos * 8 + 2 * j + half] * rden[j];
            float4 hv = h4[s * 128 + j * 32 + lane];
            acc[j].x = fmaf(hv.x, a, acc[j].x);
            acc[j].y = fmaf(hv.y, a, acc[j].y);
            acc[j].z = fmaf(hv.z, a, acc[j].z);
            acc[j].w = fmaf(hv.w, a, acc[j].w);
        }
    }

    #pragma unroll
    for (int j = 0; j < 4; j++)
        out4[d * 128 + j * 32 + lane] = acc[j];
}

// ---------------- host launch ----------------------------------------------
extern "C" void kernel_launch(void* const* d_in, const int* in_sizes, int n_in,
                              void* d_out, int out_size) {
    const float* x    = (const float*)d_in[0];   // [32768, 118]
    const int*   src  = (const int*)  d_in[2];
    const int*   dst  = (const int*)  d_in[3];
    const float* Wn   = (const float*)d_in[4];   // [118, 512]
    const float* bn   = (const float*)d_in[5];
    const float* Wa   = (const float*)d_in[8];   // [1024, 512]
    const float* ba   = (const float*)d_in[9];
    const float* attn = (const float*)d_in[10];  // [8, 64]

    float *h0, *h1, *p, *q;
    __nv_bfloat16 *ahi, *alo, *xhi, *xlo, *wnh, *wnl, *wth, *wtl, *wbh, *wbl;
    int *deg;
    cudaGetSymbolAddress((void**)&h0, g_h0);
    cudaGetSymbolAddress((void**)&h1, g_h1);
    cudaGetSymbolAddress((void**)&p,  g_p);
    cudaGetSymbolAddress((void**)&q,  g_q);
    cudaGetSymbolAddress((void**)&ahi, g_ahi);
    cudaGetSymbolAddress((void**)&alo, g_alo);
    cudaGetSymbolAddress((void**)&xhi, g_xhi);
    cudaGetSymbolAddress((void**)&xlo, g_xlo);
    cudaGetSymbolAddress((void**)&wnh, g_wn_hi);
    cudaGetSymbolAddress((void**)&wnl, g_wn_lo);
    cudaGetSymbolAddress((void**)&wth, g_wt_hi);
    cudaGetSymbolAddress((void**)&wtl, g_wt_lo);
    cudaGetSymbolAddress((void**)&wbh, g_wb_hi);
    cudaGetSymbolAddress((void**)&wbl, g_wb_lo);
    cudaGetSymbolAddress((void**)&deg, g_deg);

    // --- sort edges by dst ---
    cudaMemsetAsync(deg, 0, N_NODES * sizeof(int));
    hist_kernel<<<(N_EDGES + 255) / 256, 256>>>(dst);
    scan_kernel<<<1, 1024>>>();
    scatter_kernel<<<(N_EDGES + 255) / 256, 256>>>(src, dst);

    // --- weight prep (transpose + hi/lo split) ---
    transpose_split_kernel<<<(512 * 128 + 255) / 256, 256>>>(Wn, 118, 128, wnh, wnl);
    transpose_split_kernel<<<(512 * 512 + 255) / 256, 256>>>(Wa,             512, 512, wth, wtl);
    transpose_split_kernel<<<(512 * 512 + 255) / 256, 256>>>(Wa + 512 * 512, 512, 512, wbh, wbl);
    split_pad_x_kernel<<<(N_NODES * 128) / 256, 256>>>(x);

    dim3 ggrid(4, 256);   // N-tiles x M-tiles

    // --- h0 = x @ Wn + bn ---
    gemm_mma_kernel<<<ggrid, 256>>>(xhi, xlo, wnh, wnl, bn, h0, 128);

    // --- layer 0 ---
    split_h_kernel<<<(N_NODES * HC / 4) / 256, 256>>>((const float4*)h0, (uint2*)ahi, (uint2*)alo);
    gemm_mma_kernel<<<ggrid, 256>>>(ahi, alo, wth, wtl, nullptr, p, 512);
    gemm_mma_kernel<<<ggrid, 256>>>(ahi, alo, wbh, wbl, ba,      q, 512);
    edge_kernel<<<N_NODES / 8, 256>>>((const float4*)p, (const float4*)q,
                                      (const float4*)attn, (const float4*)h0,
                                      (float4*)h1);

    // --- layer 1 ---
    split_h_kernel<<<(N_NODES * HC / 4) / 256, 256>>>((const float4*)h1, (uint2*)ahi, (uint2*)alo);
    gemm_mma_kernel<<<ggrid, 256>>>(ahi, alo, wth, wtl, nullptr, p, 512);
    gemm_mma_kernel<<<ggrid, 256>>>(ahi, alo, wbh, wbl, ba,      q, 512);
    edge_kernel<<<N_NODES / 8, 256>>>((const float4*)p, (const float4*)q,
                                      (const float4*)attn, (const float4*)h1,
                                      (float4*)d_out);
}

// round 15
// speedup vs baseline: 2.5441x; 1.0765x over previous
#include <cuda_runtime.h>
#include <cuda_bf16.h>
#include <math.h>
#include <stdint.h>

#define N_NODES 32768
#define N_EDGES 262144
#define HC 512

// ---------------- scratch (device globals: allocation-free) ----------------
__device__ __align__(16) float g_h0[N_NODES * HC];
__device__ __align__(16) float g_h1[N_NODES * HC];
__device__ __align__(16) float g_p [N_NODES * HC];
__device__ __align__(16) float g_q [N_NODES * HC];
__device__ __align__(16) __nv_bfloat16 g_ahi[N_NODES * HC];      // split of h
__device__ __align__(16) __nv_bfloat16 g_alo[N_NODES * HC];
__device__ __align__(16) __nv_bfloat16 g_xhi[N_NODES * 128];     // split of x (K padded 118->128)
__device__ __align__(16) __nv_bfloat16 g_xlo[N_NODES * 128];
__device__ __align__(16) __nv_bfloat16 g_wn_hi[512 * 128];       // Wn^T split, [N=512, Kpad=128]
__device__ __align__(16) __nv_bfloat16 g_wn_lo[512 * 128];
__device__ __align__(16) __nv_bfloat16 g_wt_hi[512 * 512];       // Wa_top^T split
__device__ __align__(16) __nv_bfloat16 g_wt_lo[512 * 512];
__device__ __align__(16) __nv_bfloat16 g_wb_hi[512 * 512];       // Wa_bot^T split
__device__ __align__(16) __nv_bfloat16 g_wb_lo[512 * 512];
__device__ float g_ex[N_EDGES * 8];
__device__ int   g_deg[N_NODES];
__device__ int   g_rowptr[N_NODES + 1];
__device__ int   g_cursor[N_NODES];
__device__ int   g_ssrc[N_EDGES];

// ---------------- warp-MMA helpers (baseline PTX, works on plain sm_103) ---
__device__ __forceinline__ uint32_t smem_u32(const void* p) {
    uint32_t a;
    asm("{ .reg .u64 t; cvta.to.shared.u64 t, %1; cvt.u32.u64 %0, t; }" : "=r"(a) : "l"(p));
    return a;
}
__device__ __forceinline__ void ldsm_x4(uint32_t* r, uint32_t addr) {
    asm volatile("ldmatrix.sync.aligned.m8n8.x4.shared.b16 {%0,%1,%2,%3}, [%4];"
                 : "=r"(r[0]), "=r"(r[1]), "=r"(r[2]), "=r"(r[3]) : "r"(addr));
}
__device__ __forceinline__ void mma16816(float* c, const uint32_t* a, const uint32_t* b) {
    asm volatile(
        "mma.sync.aligned.m16n8k16.row.col.f32.bf16.bf16.f32 "
        "{%0,%1,%2,%3}, {%4,%5,%6,%7}, {%8,%9}, {%0,%1,%2,%3};"
        : "+f"(c[0]), "+f"(c[1]), "+f"(c[2]), "+f"(c[3])
        : "r"(a[0]), "r"(a[1]), "r"(a[2]), "r"(a[3]), "r"(b[0]), "r"(b[1]));
}
__device__ __forceinline__ void cp16(uint32_t dst, const void* src) {
    asm volatile("cp.async.cg.shared.global [%0], [%1], 16;" :: "r"(dst), "l"(src));
}
__device__ __forceinline__ void cp_commit() {
    asm volatile("cp.async.commit_group;" ::: "memory");
}
template <int N>
__device__ __forceinline__ void cp_wait() {
    asm volatile("cp.async.wait_group %0;" :: "n"(N) : "memory");
}

// ---------------- sort-by-dst: histogram / scan / scatter ------------------
__global__ void hist_kernel(const int* __restrict__ dst) {
    int e = blockIdx.x * blockDim.x + threadIdx.x;
    if (e < N_EDGES) atomicAdd(&g_deg[dst[e]], 1);
}

__global__ void scan_kernel() {
    __shared__ int sdata[1024];
    int t = threadIdx.x;
    int base = t * 32;
    int local = 0;
    #pragma unroll
    for (int i = 0; i < 32; i++) local += g_deg[base + i];
    sdata[t] = local;
    __syncthreads();
    for (int off = 1; off < 1024; off <<= 1) {
        int v = (t >= off) ? sdata[t - off] : 0;
        __syncthreads();
        sdata[t] += v;
        __syncthreads();
    }
    int run = (t == 0) ? 0 : sdata[t - 1];
    #pragma unroll
    for (int i = 0; i < 32; i++) {
        g_rowptr[base + i] = run;
        g_cursor[base + i] = run;
        run += g_deg[base + i];
    }
    if (t == 1023) g_rowptr[N_NODES] = run;
}

__global__ void scatter_kernel(const int* __restrict__ src, const int* __restrict__ dst) {
    int e = blockIdx.x * blockDim.x + threadIdx.x;
    if (e < N_EDGES) {
        int pos = atomicAdd(&g_cursor[dst[e]], 1);
        g_ssrc[pos] = src[e];
    }
}

// ---------------- fp32 -> bf16 hi/lo split helpers --------------------------
__device__ __forceinline__ void split1(float f, uint16_t& h, uint16_t& l) {
    __nv_bfloat16 bh = __float2bfloat16(f);
    float r = f - __bfloat162float(bh);
    __nv_bfloat16 bl = __float2bfloat16(r);
    h = *reinterpret_cast<uint16_t*>(&bh);
    l = *reinterpret_cast<uint16_t*>(&bl);
}
__device__ __forceinline__ uint32_t pack_hi2(float a, float b) {
    uint16_t h0, l0, h1, l1;
    split1(a, h0, l0); split1(b, h1, l1);
    return (uint32_t)h0 | ((uint32_t)h1 << 16);
}
__device__ __forceinline__ uint32_t pack_lo2(float a, float b) {
    uint16_t h0, l0, h1, l1;
    split1(a, h0, l0); split1(b, h1, l1);
    return (uint32_t)l0 | ((uint32_t)l1 << 16);
}

__global__ __launch_bounds__(256)
void split_pad_x_kernel(const float* __restrict__ x) {
    int i = blockIdx.x * blockDim.x + threadIdx.x;     // over N*128
    int r = i >> 7, c = i & 127;
    float v = (c < 118) ? x[r * 118 + c] : 0.f;
    uint16_t h, l; split1(v, h, l);
    *reinterpret_cast<uint16_t*>(&g_xhi[i]) = h;
    *reinterpret_cast<uint16_t*>(&g_xlo[i]) = l;
}

__global__ __launch_bounds__(256)
void transpose_split_kernel(const float* __restrict__ W, int K, int Kpad,
                            __nv_bfloat16* __restrict__ bh, __nv_bfloat16* __restrict__ bl) {
    int i = blockIdx.x * blockDim.x + threadIdx.x;     // over 512*Kpad
    if (i >= 512 * Kpad) return;
    int n = i / Kpad, k = i % Kpad;
    float v = (k < K) ? W[k * 512 + n] : 0.f;
    uint16_t h, l; split1(v, h, l);
    *reinterpret_cast<uint16_t*>(&bh[i]) = h;
    *reinterpret_cast<uint16_t*>(&bl[i]) = l;
}

// ---------------- HMMA bf16x3 GEMM, cp.async double-buffered ---------------
// C[M,512] = A @ B^T (+bias); C = Ahi*Bhi + Ahi*Blo + Alo*Bhi (fp32 accum).
// Optional fused second problem (B1/bias1/C1) selected by blockIdx.x>=4.
// Optional epilogue split: writes bf16 hi/lo of C (for h feeding next layer).
#define ASTR 40                    // padded smem row stride (elems) -> conflict-free ldmatrix
#define STG (128 * ASTR)           // elems per smem array per stage
#define GEMM_DSMEM (2 * 4 * STG * 2)   // 2 stages x 4 arrays x bf16 = 81920 B

__global__ __launch_bounds__(256, 2)
void gemm_mma_kernel(const __nv_bfloat16* __restrict__ Ahi, const __nv_bfloat16* __restrict__ Alo,
                     const __nv_bfloat16* __restrict__ Bhi0, const __nv_bfloat16* __restrict__ Blo0,
                     const float* __restrict__ bias0, float* __restrict__ C0,
                     const __nv_bfloat16* __restrict__ Bhi1, const __nv_bfloat16* __restrict__ Blo1,
                     const float* __restrict__ bias1, float* __restrict__ C1,
                     __nv_bfloat16* __restrict__ hi_out, __nv_bfloat16* __restrict__ lo_out,
                     int ldk) {
    extern __shared__ __nv_bfloat16 dyn[];
    // layout: [stage][Ahi,Alo,Bhi,Blo][STG]
    const int tid  = threadIdx.x;
    const int lane = tid & 31;
    const int wid  = tid >> 5;
    const int wr   = wid >> 1;
    const int wc   = wid & 1;
    const int row0 = blockIdx.y * 128;
    const bool second = (blockIdx.x >= 4);
    const int col0 = (blockIdx.x & 3) * 128;

    const __nv_bfloat16* Bhi = second ? Bhi1 : Bhi0;
    const __nv_bfloat16* Blo = second ? Blo1 : Blo0;
    const float* bias = second ? bias1 : bias0;
    float* C = second ? C1 : C0;

    float acc[2][8][4];
    #pragma unroll
    for (int mt = 0; mt < 2; mt++)
        #pragma unroll
        for (int nt = 0; nt < 8; nt++)
            #pragma unroll
            for (int k = 0; k < 4; k++) acc[mt][nt][k] = 0.f;

    const int r  = tid >> 2;          // 0..63
    const int c8 = (tid & 3) * 8;     // 0,8,16,24
    const int stages = ldk >> 5;

    const __nv_bfloat16* gA[2] = { Ahi + (size_t)row0 * ldk, Alo + (size_t)row0 * ldk };
    const __nv_bfloat16* gB[2] = { Bhi + (size_t)col0 * ldk, Blo + (size_t)col0 * ldk };

    // issue cp.async for stage kt into buffer s
    auto issue = [&](int kt, int s) {
        const size_t kofs = (size_t)kt * 32 + c8;
        uint32_t sb = smem_u32(dyn) + (uint32_t)(s * 4 * STG * 2);
        #pragma unroll
        for (int i = 0; i < 2; i++) {
            int rr = r + i * 64;
            uint32_t so = (uint32_t)(rr * ASTR + c8) * 2;
            cp16(sb + 0 * STG * 2 + so, gA[0] + (size_t)rr * ldk + kofs);
            cp16(sb + 1 * STG * 2 + so, gA[1] + (size_t)rr * ldk + kofs);
            cp16(sb + 2 * STG * 2 + so, gB[0] + (size_t)rr * ldk + kofs);
            cp16(sb + 3 * STG * 2 + so, gB[1] + (size_t)rr * ldk + kofs);
        }
        cp_commit();
    };

    issue(0, 0);

    for (int kt = 0; kt < stages; kt++) {
        const int s = kt & 1;
        if (kt + 1 < stages) { issue(kt + 1, s ^ 1); cp_wait<1>(); }
        else                 { cp_wait<0>(); }
        __syncthreads();

        __nv_bfloat16* sAhi = dyn + (s * 4 + 0) * STG;
        __nv_bfloat16* sAlo = dyn + (s * 4 + 1) * STG;
        __nv_bfloat16* sBhi = dyn + (s * 4 + 2) * STG;
        __nv_bfloat16* sBlo = dyn + (s * 4 + 3) * STG;

        #pragma unroll
        for (int kc = 0; kc < 2; kc++) {
            uint32_t af[2][2][4];
            {
                int arow = wr * 32 + (lane & 7) + ((lane >> 3) & 1) * 8;
                int akol = kc * 16 + (lane >> 4) * 8;
                #pragma unroll
                for (int mt = 0; mt < 2; mt++) {
                    int o = (arow + mt * 16) * ASTR + akol;
                    ldsm_x4(af[0][mt], smem_u32(&sAhi[o]));
                    ldsm_x4(af[1][mt], smem_u32(&sAlo[o]));
                }
            }
            int nrow = wc * 64 + (lane & 7) + (lane >> 4) * 8;
            int nkol = kc * 16 + ((lane >> 3) & 1) * 8;
            #pragma unroll
            for (int np = 0; np < 4; np++) {
                uint32_t bf[2][4];
                int o = (nrow + np * 16) * ASTR + nkol;
                ldsm_x4(bf[0], smem_u32(&sBhi[o]));
                ldsm_x4(bf[1], smem_u32(&sBlo[o]));
                #pragma unroll
                for (int mt = 0; mt < 2; mt++)
                    #pragma unroll
                    for (int ss = 0; ss < 2; ss++) {
                        float* c = acc[mt][np * 2 + ss];
                        mma16816(c, af[0][mt], bf[0] + ss * 2);   // hi*hi
                        mma16816(c, af[0][mt], bf[1] + ss * 2);   // hi*lo
                        mma16816(c, af[1][mt], bf[0] + ss * 2);   // lo*hi
                    }
            }
        }
        __syncthreads();
    }

    // epilogue
    #pragma unroll
    for (int mt = 0; mt < 2; mt++) {
        int rr = row0 + wr * 32 + mt * 16 + (lane >> 2);
        #pragma unroll
        for (int nt = 0; nt < 8; nt++) {
            int cc = col0 + wc * 64 + nt * 8 + (lane & 3) * 2;
            float b0 = bias ? bias[cc]     : 0.f;
            float b1 = bias ? bias[cc + 1] : 0.f;
            float v0 = acc[mt][nt][0] + b0, v1 = acc[mt][nt][1] + b1;
            float v2 = acc[mt][nt][2] + b0, v3 = acc[mt][nt][3] + b1;
            size_t o01 = (size_t)rr * HC + cc;
            size_t o23 = (size_t)(rr + 8) * HC + cc;
            *(float2*)&C[o01] = make_float2(v0, v1);
            *(float2*)&C[o23] = make_float2(v2, v3);
            if (hi_out) {
                *(uint32_t*)&hi_out[o01] = pack_hi2(v0, v1);
                *(uint32_t*)&hi_out[o23] = pack_hi2(v2, v3);
                *(uint32_t*)&lo_out[o01] = pack_lo2(v0, v1);
                *(uint32_t*)&lo_out[o23] = pack_lo2(v2, v3);
            }
        }
    }
}

// ---------------- fused per-dst attention + aggregation ---------------------
__device__ __forceinline__ float lrelu(float v) { return v > 0.f ? v : 0.01f * v; }

__global__ __launch_bounds__(256)
void edge_kernel(const float4* __restrict__ p4, const float4* __restrict__ q4,
                 const float4* __restrict__ w4, const float4* __restrict__ h4,
                 float4* __restrict__ out4,
                 uint2* __restrict__ hi4, uint2* __restrict__ lo4) {
    int warp = (blockIdx.x * blockDim.x + threadIdx.x) >> 5;
    int lane = threadIdx.x & 31;
    if (warp >= N_NODES) return;
    int d = warp;
    int start = g_rowptr[d];
    int end   = g_rowptr[d + 1];
    int half  = lane >> 4;

    float4 qv[4], wv[4];
    #pragma unroll
    for (int j = 0; j < 4; j++) {
        qv[j] = q4[d * 128 + j * 32 + lane];
        wv[j] = w4[j * 32 + lane];
    }

    float den[4] = {0.f, 0.f, 0.f, 0.f};
    for (int pos = start; pos < end; pos++) {
        int s = g_ssrc[pos];
        #pragma unroll
        for (int j = 0; j < 4; j++) {
            float4 pv = p4[s * 128 + j * 32 + lane];
            float part = lrelu(pv.x + qv[j].x) * wv[j].x
                       + lrelu(pv.y + qv[j].y) * wv[j].y
                       + lrelu(pv.z + qv[j].z) * wv[j].z
                       + lrelu(pv.w + qv[j].w) * wv[j].w;
            #pragma unroll
            for (int off = 8; off >= 1; off >>= 1)
                part += __shfl_xor_sync(0xffffffffu, part, off);
            float ex = expf(part);
            den[j] += ex;
            if ((lane & 15) == j)
                g_ex[pos * 8 + 2 * j + half] = ex;
        }
    }
    __syncwarp();

    float rden[4];
    #pragma unroll
    for (int j = 0; j < 4; j++) rden[j] = (den[j] > 0.f) ? (1.f / den[j]) : 0.f;

    float4 acc[4];
    #pragma unroll
    for (int j = 0; j < 4; j++) acc[j] = make_float4(0.f, 0.f, 0.f, 0.f);

    for (int pos = start; pos < end; pos++) {
        int s = g_ssrc[pos];
        #pragma unroll
        for (int j = 0; j < 4; j++) {
            float a = g_ex[pos * 8 + 2 * j + half] * rden[j];
            float4 hv = h4[s * 128 + j * 32 + lane];
            acc[j].x = fmaf(hv.x, a, acc[j].x);
            acc[j].y = fmaf(hv.y, a, acc[j].y);
            acc[j].z = fmaf(hv.z, a, acc[j].z);
            acc[j].w = fmaf(hv.w, a, acc[j].w);
        }
    }

    #pragma unroll
    for (int j = 0; j < 4; j++) {
        int i4 = d * 128 + j * 32 + lane;
        out4[i4] = acc[j];
        if (hi4) {
            hi4[i4] = make_uint2(pack_hi2(acc[j].x, acc[j].y), pack_hi2(acc[j].z, acc[j].w));
            lo4[i4] = make_uint2(pack_lo2(acc[j].x, acc[j].y), pack_lo2(acc[j].z, acc[j].w));
        }
    }
}

// ---------------- host launch ----------------------------------------------
extern "C" void kernel_launch(void* const* d_in, const int* in_sizes, int n_in,
                              void* d_out, int out_size) {
    const float* x    = (const float*)d_in[0];   // [32768, 118]
    const int*   src  = (const int*)  d_in[2];
    const int*   dst  = (const int*)  d_in[3];
    const float* Wn   = (const float*)d_in[4];   // [118, 512]
    const float* bn   = (const float*)d_in[5];
    const float* Wa   = (const float*)d_in[8];   // [1024, 512]
    const float* ba   = (const float*)d_in[9];
    const float* attn = (const float*)d_in[10];  // [8, 64]

    float *h0, *h1, *p, *q;
    __nv_bfloat16 *ahi, *alo, *xhi, *xlo, *wnh, *wnl, *wth, *wtl, *wbh, *wbl;
    int *deg;
    cudaGetSymbolAddress((void**)&h0, g_h0);
    cudaGetSymbolAddress((void**)&h1, g_h1);
    cudaGetSymbolAddress((void**)&p,  g_p);
    cudaGetSymbolAddress((void**)&q,  g_q);
    cudaGetSymbolAddress((void**)&ahi, g_ahi);
    cudaGetSymbolAddress((void**)&alo, g_alo);
    cudaGetSymbolAddress((void**)&xhi, g_xhi);
    cudaGetSymbolAddress((void**)&xlo, g_xlo);
    cudaGetSymbolAddress((void**)&wnh, g_wn_hi);
    cudaGetSymbolAddress((void**)&wnl, g_wn_lo);
    cudaGetSymbolAddress((void**)&wth, g_wt_hi);
    cudaGetSymbolAddress((void**)&wtl, g_wt_lo);
    cudaGetSymbolAddress((void**)&wbh, g_wb_hi);
    cudaGetSymbolAddress((void**)&wbl, g_wb_lo);
    cudaGetSymbolAddress((void**)&deg, g_deg);

    cudaFuncSetAttribute(gemm_mma_kernel,
                         cudaFuncAttributeMaxDynamicSharedMemorySize, GEMM_DSMEM);

    // --- sort edges by dst ---
    cudaMemsetAsync(deg, 0, N_NODES * sizeof(int));
    hist_kernel<<<(N_EDGES + 255) / 256, 256>>>(dst);
    scan_kernel<<<1, 1024>>>();
    scatter_kernel<<<(N_EDGES + 255) / 256, 256>>>(src, dst);

    // --- weight prep (transpose + hi/lo split) ---
    transpose_split_kernel<<<(512 * 128 + 255) / 256, 256>>>(Wn, 118, 128, wnh, wnl);
    transpose_split_kernel<<<(512 * 512 + 255) / 256, 256>>>(Wa,             512, 512, wth, wtl);
    transpose_split_kernel<<<(512 * 512 + 255) / 256, 256>>>(Wa + 512 * 512, 512, 512, wbh, wbl);
    split_pad_x_kernel<<<(N_NODES * 128) / 256, 256>>>(x);

    // --- h0 = x @ Wn + bn  (epilogue also emits bf16 split of h0) ---
    gemm_mma_kernel<<<dim3(4, 256), 256, GEMM_DSMEM>>>(
        xhi, xlo, wnh, wnl, bn, h0,
        nullptr, nullptr, nullptr, nullptr, ahi, alo, 128);

    // --- layer 0: fused p/q GEMM, then edge (emits split of h1) ---
    gemm_mma_kernel<<<dim3(8, 256), 256, GEMM_DSMEM>>>(
        ahi, alo, wth, wtl, nullptr, p,
        wbh, wbl, ba, q, nullptr, nullptr, 512);
    edge_kernel<<<N_NODES / 8, 256>>>((const float4*)p, (const float4*)q,
                                      (const float4*)attn, (const float4*)h0,
                                      (float4*)h1, (uint2*)ahi, (uint2*)alo);

    // --- layer 1 ---
    gemm_mma_kernel<<<dim3(8, 256), 256, GEMM_DSMEM>>>(
        ahi, alo, wth, wtl, nullptr, p,
        wbh, wbl, ba, q, nullptr, nullptr, 512);
    edge_kernel<<<N_NODES / 8, 256>>>((const float4*)p, (const float4*)q,
                                      (const float4*)attn, (const float4*)h1,
                                      (float4*)d_out, nullptr, nullptr);
}